// round 3
// baseline (speedup 1.0000x reference)
#include <cuda_runtime.h>
#include <math.h>
#include <stdint.h>

// Problem constants
#define BB 128     // batch
#define SS 256     // seq len
#define DD 512     // embed dim
#define HH 1024    // hidden
#define NCC 128    // num classes (output)
#define NCLS 129   // embedding rows (0..128)

// Recurrence kernel config
#define RGRID 128      // persistent CTAs (<= #SMs, co-resident)
#define RTHREADS 128
#define KT 32          // k-chunk staged in smem
#define NCHUNK (HH / KT)

// ---------------- device scratch (static allocations only) ----------------
__device__ float d_P[(size_t)NCLS * HH * 4];     // P[class][col][gate]  (~2.1 MB)
__device__ float d_Wp[(size_t)HH * HH * 4];      // packed recurrent weights: Wp[k][col][gate] (16 MB)
__device__ int   d_xT[SS * BB];                  // x transposed [t][b]
__device__ float d_hT[2][HH * BB];               // h double buffer, layout [k][b]
__device__ unsigned d_bar_arrive = 0;
__device__ unsigned d_bar_gen = 0;

// ---------------- helpers ----------------
__device__ __forceinline__ float sigf(float x) {
    return 1.0f / (1.0f + __expf(-x));
}
__device__ __forceinline__ float tanh_s(float x) {
    // overflow-safe tanh via exp of negative magnitude
    float a = fabsf(x);
    float e = __expf(-2.0f * a);
    float r = (1.0f - e) / (1.0f + e);
    return copysignf(r, x);
}

__device__ __forceinline__ void cpa16(void* smem_dst, const void* gsrc) {
    unsigned d = (unsigned)__cvta_generic_to_shared(smem_dst);
    asm volatile("cp.async.cg.shared.global [%0], [%1], 16;" :: "r"(d), "l"(gsrc));
}

__device__ __forceinline__ void grid_sync_all(unsigned G) {
    __threadfence();
    __syncthreads();
    if (threadIdx.x == 0) {
        unsigned gen = atomicAdd(&d_bar_gen, 0u);
        if (atomicAdd(&d_bar_arrive, 1u) == G - 1u) {
            atomicExch(&d_bar_arrive, 0u);
            __threadfence();
            atomicAdd(&d_bar_gen, 1u);
        } else {
            while (atomicAdd(&d_bar_gen, 0u) == gen) { }
        }
        __threadfence();
    }
    __syncthreads();
}

// ---------------- prep kernels ----------------

// zero h buffer 0, build xT
__global__ void k_misc(const int* __restrict__ x) {
    int i = blockIdx.x * 256 + threadIdx.x;
    if (i < HH * BB) d_hT[0][i] = 0.0f;
    if (i < SS * BB) {
        int t = i >> 7;       // /BB
        int b = i & 127;      // %BB
        d_xT[i] = x[b * SS + t];   // x is [B,S,1]
    }
}

// pack 4 recurrent weight matrices into gate-interleaved layout
__global__ void k_pack(const float* __restrict__ Wfh, const float* __restrict__ Wih,
                       const float* __restrict__ Wgh, const float* __restrict__ Woh) {
    int i = blockIdx.x * 256 + threadIdx.x;
    if (i < HH * HH) {
        float4 v = make_float4(Wfh[i], Wih[i], Wgh[i], Woh[i]);
        *(float4*)(d_Wp + 4 * (size_t)i) = v;
    }
}

// P[c][col][g] = bias_g[col] + sum_d emb[c][d] * Wx_g[d][col]
__global__ void k_precomp(const float* __restrict__ emb,
                          const float* __restrict__ Wfx, const float* __restrict__ Wix,
                          const float* __restrict__ Wgx, const float* __restrict__ Wox,
                          const float* __restrict__ bfv, const float* __restrict__ biv,
                          const float* __restrict__ bgv, const float* __restrict__ bov) {
    __shared__ float es[16][32];
    const int tid = threadIdx.x;
    const int col = blockIdx.x * 128 + tid;
    const int c0  = blockIdx.y * 16;

    float acc[16][4];
#pragma unroll
    for (int ci = 0; ci < 16; ci++)
#pragma unroll
        for (int g = 0; g < 4; g++) acc[ci][g] = 0.0f;

    for (int k0 = 0; k0 < DD; k0 += 32) {
        for (int q = tid; q < 16 * 32; q += 128) {
            int ci = q >> 5, kk = q & 31;
            int c = c0 + ci;
            es[ci][kk] = (c < NCLS) ? emb[(size_t)c * DD + k0 + kk] : 0.0f;
        }
        __syncthreads();
#pragma unroll 4
        for (int kk = 0; kk < 32; kk++) {
            int d = k0 + kk;
            float wf = Wfx[(size_t)d * HH + col];
            float wi = Wix[(size_t)d * HH + col];
            float wg = Wgx[(size_t)d * HH + col];
            float wo = Wox[(size_t)d * HH + col];
#pragma unroll
            for (int ci = 0; ci < 16; ci++) {
                float e = es[ci][kk];
                acc[ci][0] = fmaf(e, wf, acc[ci][0]);
                acc[ci][1] = fmaf(e, wi, acc[ci][1]);
                acc[ci][2] = fmaf(e, wg, acc[ci][2]);
                acc[ci][3] = fmaf(e, wo, acc[ci][3]);
            }
        }
        __syncthreads();
    }
    float b0v = bfv[col], b1v = biv[col], b2v = bgv[col], b3v = bov[col];
#pragma unroll
    for (int ci = 0; ci < 16; ci++) {
        int c = c0 + ci;
        if (c < NCLS) {
            float4 v = make_float4(acc[ci][0] + b0v, acc[ci][1] + b1v,
                                   acc[ci][2] + b2v, acc[ci][3] + b3v);
            *(float4*)(d_P + ((size_t)c * HH + col) * 4) = v;
        }
    }
}

// ---------------- persistent recurrence ----------------
// 128 CTAs; CTA owns 8 h-columns (x4 gates = 32 output cols).
// 128 threads: tid = bg*8 + og; og -> column (1 of 8), bg -> 8 batch rows.
// C state stays in registers for the whole scan.

#define GATE_FMA(gi, wc)                                   \
    acc[0][gi] = fmaf(ha.x, wc, acc[0][gi]);               \
    acc[1][gi] = fmaf(ha.y, wc, acc[1][gi]);               \
    acc[2][gi] = fmaf(ha.z, wc, acc[2][gi]);               \
    acc[3][gi] = fmaf(ha.w, wc, acc[3][gi]);               \
    acc[4][gi] = fmaf(hb.x, wc, acc[4][gi]);               \
    acc[5][gi] = fmaf(hb.y, wc, acc[5][gi]);               \
    acc[6][gi] = fmaf(hb.z, wc, acc[6][gi]);               \
    acc[7][gi] = fmaf(hb.w, wc, acc[7][gi]);

__global__ void __launch_bounds__(RTHREADS, 1) k_recur() {
    __shared__ __align__(16) float hs[2][KT][BB];   // 32 KB
    __shared__ __align__(16) float ws[2][KT][32];   // 8 KB

    const int tid = threadIdx.x;
    const int og  = tid & 7;
    const int bg  = tid >> 3;
    const int b0  = bg * 8;
    const int bq  = b0 >> 2;       // float4 index into a 128-wide h row
    const int col0 = blockIdx.x * 8;
    const int col  = col0 + og;

    float C[8];
#pragma unroll
    for (int j = 0; j < 8; j++) C[j] = 0.0f;

    for (int t = 0; t < SS; t++) {
        const float* hbase = d_hT[t & 1];

        float acc[8][4];
#pragma unroll
        for (int j = 0; j < 8; j++)
#pragma unroll
            for (int g = 0; g < 4; g++) acc[j][g] = 0.0f;

        // preload chunk 0
        {
            const int k0 = 0;
            float* hdst = &hs[0][0][0];
            const float* hsrc = hbase + (size_t)k0 * BB;
#pragma unroll
            for (int j = 0; j < 8; j++) {
                int q = tid + j * 128;
                cpa16(hdst + q * 4, hsrc + (size_t)q * 4);
            }
            float* wdst = &ws[0][0][0];
#pragma unroll
            for (int j = 0; j < 2; j++) {
                int q = tid + j * 128;
                int kk = q >> 3, m = q & 7;
                cpa16(wdst + q * 4, d_Wp + ((size_t)(k0 + kk) * 4096 + col0 * 4 + m * 4));
            }
            asm volatile("cp.async.commit_group;");
        }

        for (int ci = 0; ci < NCHUNK; ci++) {
            if (ci + 1 < NCHUNK) {
                const int k0 = (ci + 1) * KT;
                const int bb = (ci + 1) & 1;
                float* hdst = &hs[bb][0][0];
                const float* hsrc = hbase + (size_t)k0 * BB;
#pragma unroll
                for (int j = 0; j < 8; j++) {
                    int q = tid + j * 128;
                    cpa16(hdst + q * 4, hsrc + (size_t)q * 4);
                }
                float* wdst = &ws[bb][0][0];
#pragma unroll
                for (int j = 0; j < 2; j++) {
                    int q = tid + j * 128;
                    int kk = q >> 3, m = q & 7;
                    cpa16(wdst + q * 4, d_Wp + ((size_t)(k0 + kk) * 4096 + col0 * 4 + m * 4));
                }
                asm volatile("cp.async.commit_group;");
                asm volatile("cp.async.wait_group 1;");
            } else {
                asm volatile("cp.async.wait_group 0;");
            }
            __syncthreads();

            const float4* h4 = (const float4*)&hs[ci & 1][0][0];
            const float4* w4 = (const float4*)&ws[ci & 1][0][0];
#pragma unroll
            for (int kk = 0; kk < KT; kk++) {
                const float4 w  = w4[kk * 8 + og];
                const float4 ha = h4[kk * 32 + bq];
                const float4 hb = h4[kk * 32 + bq + 1];
                GATE_FMA(0, w.x)
                GATE_FMA(1, w.y)
                GATE_FMA(2, w.z)
                GATE_FMA(3, w.w)
            }
            __syncthreads();
        }

        // epilogue: gates, cell update (registers), write new h
        const int xoff = t * BB;
        float hn[8];
#pragma unroll
        for (int j = 0; j < 8; j++) {
            int cls = d_xT[xoff + b0 + j];
            float4 pg = *(const float4*)(d_P + ((size_t)cls * HH + col) * 4);
            float f  = sigf(acc[j][0] + pg.x);
            float ii = sigf(acc[j][1] + pg.y);
            float gg = sigf(acc[j][2] + pg.z);
            float oo = sigf(acc[j][3] + pg.w);
            float Cn = fmaf(gg, ii, C[j] * f);
            Cn = (cls > 0) ? Cn : 0.0f;
            C[j] = Cn;
            hn[j] = oo * tanh_s(Cn);
        }
        float* wout = d_hT[(t + 1) & 1] + (size_t)col * BB + b0;
        *(float4*)(wout)     = make_float4(hn[0], hn[1], hn[2], hn[3]);
        *(float4*)(wout + 4) = make_float4(hn[4], hn[5], hn[6], hn[7]);

        grid_sync_all(RGRID);
    }
}

// ---------------- head: p = h @ Wph + bp ; log_softmax over classes ----------------
__global__ void k_head(const float* __restrict__ Wph, const float* __restrict__ bp,
                       float* __restrict__ out) {
    __shared__ float h_s[HH];
    __shared__ float red[128];
    const int b = blockIdx.x;
    const int n = threadIdx.x;

    // final h lives in buffer (SS & 1) == 0; layout [k][b]
    for (int i = n; i < HH; i += 128) h_s[i] = d_hT[0][(size_t)i * BB + b];
    __syncthreads();

    float p = bp[n];
#pragma unroll 8
    for (int k = 0; k < HH; k++) p = fmaf(h_s[k], Wph[(size_t)k * NCC + n], p);

    red[n] = p;
    __syncthreads();
    for (int s = 64; s > 0; s >>= 1) {
        if (n < s) red[n] = fmaxf(red[n], red[n + s]);
        __syncthreads();
    }
    float mx = red[0];
    __syncthreads();
    red[n] = __expf(p - mx);
    __syncthreads();
    for (int s = 64; s > 0; s >>= 1) {
        if (n < s) red[n] += red[n + s];
        __syncthreads();
    }
    float lse = mx + logf(red[0]);
    out[(size_t)b * NCC + n] = p - lse;
}

// ---------------- launch ----------------
extern "C" void kernel_launch(void* const* d_in, const int* in_sizes, int n_in,
                              void* d_out, int out_size) {
    const int*   x   = (const int*)d_in[0];
    const float* emb = (const float*)d_in[1];
    const float* Wfx = (const float*)d_in[2];
    const float* Wfh = (const float*)d_in[3];
    const float* bf  = (const float*)d_in[4];
    const float* Wix = (const float*)d_in[5];
    const float* Wih = (const float*)d_in[6];
    const float* bi  = (const float*)d_in[7];
    const float* Wgx = (const float*)d_in[8];
    const float* Wgh = (const float*)d_in[9];
    const float* bg  = (const float*)d_in[10];
    const float* Wox = (const float*)d_in[11];
    const float* Woh = (const float*)d_in[12];
    const float* bo  = (const float*)d_in[13];
    const float* Wph = (const float*)d_in[14];
    const float* bp  = (const float*)d_in[15];
    float* out = (float*)d_out;

    k_misc<<<512, 256>>>(x);
    k_pack<<<(HH * HH + 255) / 256, 256>>>(Wfh, Wih, Wgh, Woh);
    dim3 gP(8, 9);
    k_precomp<<<gP, 128>>>(emb, Wfx, Wix, Wgx, Wox, bf, bi, bg, bo);
    k_recur<<<RGRID, RTHREADS>>>();
    k_head<<<NCC, 128>>>(Wph, bp, out);
}

// round 7
// speedup vs baseline: 2.4233x; 2.4233x over previous
#include <cuda_runtime.h>
#include <cuda_bf16.h>
#include <math.h>
#include <stdint.h>

// Problem constants
#define BB 128     // batch
#define SS 256     // seq len
#define DD 512     // embed dim
#define HH 1024    // hidden
#define NCC 128    // num classes
#define NCLS 129   // embedding rows

// Recurrence config
#define RGRID 64       // persistent CTAs, each owns 16 h-cols (64 gate-cols)
#define RTHREADS 128   // 4 warps
#define HCPC 16        // h-cols per CTA
#define HROW 2048      // bytes per h row (1024 bf16)

// SMEM: 16 resident weight tiles (64n x 64k bf16, 8KB, SW128)
//       3 A tiles (128m x 64k bf16, 16KB, SW128)  +  D buffer 128 x 68 fp32
#define W_BYTES (16 * 8192)
#define A_TILE  16384
#define D_ROW   272
#define D_BYTES (128 * D_ROW)
#define SMEM_DYN (W_BYTES + 3 * A_TILE + D_BYTES + 1024)

#define SWZ(o) ((o) ^ (((o) >> 3) & 0x70))

// ---------------- device scratch ----------------
__device__ float d_P[(size_t)NCLS * HH * 4];     // P[class][col][gate]
__device__ float d_Wp[(size_t)HH * HH * 4];      // Wp[k][col][gate] fp32
__device__ int   d_xT[SS * BB];                  // x transposed [t][b]
__device__ __nv_bfloat16 d_hbf[2][BB * HH];      // h double buffer, [b][k] bf16
__device__ float d_hfin[BB * HH];                // final-step h fp32 [b][k]
__device__ unsigned d_bar_arrive = 0;
__device__ unsigned d_bar_gen = 0;

// ---------------- helpers ----------------
__device__ __forceinline__ uint32_t smem_u32(const void* p) {
    uint32_t a;
    asm("{ .reg .u64 t; cvta.to.shared.u64 t, %1; cvt.u32.u64 %0, t; }" : "=r"(a) : "l"(p));
    return a;
}
__device__ __forceinline__ void ldsm4(uint32_t& r0, uint32_t& r1, uint32_t& r2, uint32_t& r3,
                                      uint32_t addr) {
    asm volatile("ldmatrix.sync.aligned.m8n8.x4.shared.b16 {%0,%1,%2,%3}, [%4];"
                 : "=r"(r0), "=r"(r1), "=r"(r2), "=r"(r3) : "r"(addr));
}
__device__ __forceinline__ void mma16816(float* d, const uint32_t* a, uint32_t b0, uint32_t b1) {
    asm volatile("mma.sync.aligned.m16n8k16.row.col.f32.bf16.bf16.f32 "
                 "{%0,%1,%2,%3}, {%4,%5,%6,%7}, {%8,%9}, {%0,%1,%2,%3};"
                 : "+f"(d[0]), "+f"(d[1]), "+f"(d[2]), "+f"(d[3])
                 : "r"(a[0]), "r"(a[1]), "r"(a[2]), "r"(a[3]), "r"(b0), "r"(b1));
}
__device__ __forceinline__ float sigf(float x) {
    float e = __expf(-x);
    return __fdividef(1.0f, 1.0f + e);
}
__device__ __forceinline__ float tanh_s(float x) {
    float a = fabsf(x);
    float e = __expf(-2.0f * a);
    float r = __fdividef(1.0f - e, 1.0f + e);
    return copysignf(r, x);
}

__device__ __forceinline__ void grid_sync_all(unsigned G) {
    __threadfence();
    __syncthreads();
    if (threadIdx.x == 0) {
        unsigned gen = atomicAdd(&d_bar_gen, 0u);
        if (atomicAdd(&d_bar_arrive, 1u) == G - 1u) {
            atomicExch(&d_bar_arrive, 0u);
            __threadfence();
            atomicAdd(&d_bar_gen, 1u);
        } else {
            while (atomicAdd(&d_bar_gen, 0u) == gen) { }
        }
        __threadfence();
    }
    __syncthreads();
}

// load one A tile (h k-block kt: 128 rows x 64 bf16) into SMEM buffer at dst (SW128)
__device__ __forceinline__ void load_tile(const char* hsrc, int kt, uint32_t dst, int tid) {
#pragma unroll
    for (int j = 0; j < 8; j++) {
        const int g   = tid + j * RTHREADS;       // 0..1023
        const int row = g >> 3, c16 = g & 7;
        const char* s = hsrc + (size_t)row * HROW + (size_t)kt * 128 + c16 * 16;
        uint32_t d = dst + SWZ((unsigned)(row * 128 + c16 * 16));
        asm volatile("cp.async.cg.shared.global [%0], [%1], 16;" :: "r"(d), "l"(s));
    }
}

// ---------------- prep kernels ----------------
__global__ void k_misc(const int* __restrict__ x) {
    int i = blockIdx.x * 256 + threadIdx.x;
    if (i < BB * HH / 2) ((uint32_t*)d_hbf)[i] = 0u;   // zero bf16 h buffer 0
    if (i < SS * BB) {
        int t = i >> 7, b = i & 127;
        d_xT[i] = x[b * SS + t];
    }
}

__global__ void k_pack(const float* __restrict__ Wfh, const float* __restrict__ Wih,
                       const float* __restrict__ Wgh, const float* __restrict__ Woh) {
    int i = blockIdx.x * 256 + threadIdx.x;
    if (i < HH * HH) {
        float4 v = make_float4(Wfh[i], Wih[i], Wgh[i], Woh[i]);
        *(float4*)(d_Wp + 4 * (size_t)i) = v;
    }
}

__global__ void k_precomp(const float* __restrict__ emb,
                          const float* __restrict__ Wfx, const float* __restrict__ Wix,
                          const float* __restrict__ Wgx, const float* __restrict__ Wox,
                          const float* __restrict__ bfv, const float* __restrict__ biv,
                          const float* __restrict__ bgv, const float* __restrict__ bov) {
    __shared__ float es[16][32];
    const int tid = threadIdx.x;
    const int col = blockIdx.x * 128 + tid;
    const int c0  = blockIdx.y * 16;

    float acc[16][4];
#pragma unroll
    for (int ci = 0; ci < 16; ci++)
#pragma unroll
        for (int g = 0; g < 4; g++) acc[ci][g] = 0.0f;

    for (int k0 = 0; k0 < DD; k0 += 32) {
        for (int q = tid; q < 16 * 32; q += 128) {
            int ci = q >> 5, kk = q & 31;
            int c = c0 + ci;
            es[ci][kk] = (c < NCLS) ? emb[(size_t)c * DD + k0 + kk] : 0.0f;
        }
        __syncthreads();
#pragma unroll 4
        for (int kk = 0; kk < 32; kk++) {
            int d = k0 + kk;
            float wf = Wfx[(size_t)d * HH + col];
            float wi = Wix[(size_t)d * HH + col];
            float wg = Wgx[(size_t)d * HH + col];
            float wo = Wox[(size_t)d * HH + col];
#pragma unroll
            for (int ci = 0; ci < 16; ci++) {
                float e = es[ci][kk];
                acc[ci][0] = fmaf(e, wf, acc[ci][0]);
                acc[ci][1] = fmaf(e, wi, acc[ci][1]);
                acc[ci][2] = fmaf(e, wg, acc[ci][2]);
                acc[ci][3] = fmaf(e, wo, acc[ci][3]);
            }
        }
        __syncthreads();
    }
    float b0v = bfv[col], b1v = biv[col], b2v = bgv[col], b3v = bov[col];
#pragma unroll
    for (int ci = 0; ci < 16; ci++) {
        int c = c0 + ci;
        if (c < NCLS) {
            float4 v = make_float4(acc[ci][0] + b0v, acc[ci][1] + b1v,
                                   acc[ci][2] + b2v, acc[ci][3] + b3v);
            *(float4*)(d_P + ((size_t)c * HH + col) * 4) = v;
        }
    }
}

// ---------------- persistent mma.sync recurrence ----------------
// 64 CTAs; CTA owns 64 gate-cols (16 h-cols). Weights SMEM-resident bf16 (SW128 tiles).
// Per step: D[128,64] = h[128,1024]_bf16 @ Wslice via HMMA m16n8k16, fp32 accum in regs.
// 4 warps: warp (mw,nw) computes m64 x n32.
__global__ void __launch_bounds__(RTHREADS, 1) k_recur() {
    extern __shared__ __align__(16) char dsm[];
    const int tid  = threadIdx.x;
    const int wid  = tid >> 5;
    const int lane = tid & 31;
    const int cta  = blockIdx.x;
    const int mw   = wid >> 1;      // 0..1 : m64 half
    const int nw   = wid & 1;       // 0..1 : n32 half

    uint32_t smem0 = smem_u32(dsm);
    uint32_t base  = (smem0 + 1023u) & ~1023u;
    char* dsb = dsm + (base - smem0);
    const uint32_t Wb = base;
    const uint32_t Ab = base + W_BYTES;
    char* dptr = dsb + W_BYTES + 3 * A_TILE;   // D buffer

    // ---- resident weights: tile q = k-block [64q, 64q+64); rows n=0..63, 128B rows, SW128
    for (int q = 0; q < 16; q++) {
        const float* src = d_Wp + (size_t)q * 64 * (HH * 4) + cta * 64;
        char* tile = dsb + q * 8192;
        for (int i2 = tid; i2 < 4096; i2 += RTHREADS) {
            int n = i2 & 63, kk = i2 >> 6;
            *(__nv_bfloat16*)(tile + SWZ((unsigned)(n * 128 + kk * 2))) =
                __float2bfloat16(src[(size_t)kk * (HH * 4) + n]);
        }
    }
    __syncthreads();

    // ---- lane-constant ldmatrix address pieces
    const int grp = lane >> 3, r8 = lane & 7;
    // A: x4 tiles (m0-7,k0-7)(m8-15,k0-7)(m0-7,k8-15)(m8-15,k8-15)
    uint32_t a_row[4], a_xor[4];
#pragma unroll
    for (int mt = 0; mt < 4; mt++) {
        int m = 64 * mw + 16 * mt + (grp & 1) * 8 + r8;
        a_row[mt] = (uint32_t)(m * 128);
        a_xor[mt] = (uint32_t)((m & 7) * 16);
    }
    const int cgA = grp >> 1;
    // B: x4 tiles (n0-7,k0-7)(n0-7,k8-15)(n8-15,k0-7)(n8-15,k8-15)
    uint32_t b_row[2], b_xor[2];
#pragma unroll
    for (int nt2 = 0; nt2 < 2; nt2++) {
        int n = 32 * nw + 16 * nt2 + (grp >> 1) * 8 + r8;
        b_row[nt2] = (uint32_t)(n * 128);
        b_xor[nt2] = (uint32_t)((n & 7) * 16);
    }
    const int cgB = grp & 1;

    float C[HCPC];
#pragma unroll
    for (int c = 0; c < HCPC; c++) C[c] = 0.0f;

    for (int t = 0; t < SS; t++) {
        const char* hsrc = (const char*)d_hbf[t & 1];

        load_tile(hsrc, 0, Ab + 0 * A_TILE, tid);
        asm volatile("cp.async.commit_group;");
        load_tile(hsrc, 1, Ab + 1 * A_TILE, tid);
        asm volatile("cp.async.commit_group;");

        float acc[4][4][4];
#pragma unroll
        for (int mt = 0; mt < 4; mt++)
#pragma unroll
            for (int nt = 0; nt < 4; nt++)
#pragma unroll
                for (int e = 0; e < 4; e++) acc[mt][nt][e] = 0.0f;

        for (int i = 0; i < 16; i++) {
            if (i < 15) asm volatile("cp.async.wait_group 1;");
            else        asm volatile("cp.async.wait_group 0;");
            __syncthreads();
            if (i < 14) {
                load_tile(hsrc, i + 2, Ab + ((i + 2) % 3) * A_TILE, tid);
                asm volatile("cp.async.commit_group;");
            }
            const uint32_t Abuf  = Ab + (i % 3) * A_TILE;
            const uint32_t Wtile = Wb + i * 8192;
#pragma unroll
            for (int kc = 0; kc < 4; kc++) {
                uint32_t a[4][4];
#pragma unroll
                for (int mt = 0; mt < 4; mt++)
                    ldsm4(a[mt][0], a[mt][1], a[mt][2], a[mt][3],
                          Abuf + a_row[mt] + (((unsigned)(16 * (2 * kc + cgA))) ^ a_xor[mt]));
                uint32_t bf[2][4];
#pragma unroll
                for (int nt2 = 0; nt2 < 2; nt2++)
                    ldsm4(bf[nt2][0], bf[nt2][1], bf[nt2][2], bf[nt2][3],
                          Wtile + b_row[nt2] + (((unsigned)(16 * (2 * kc + cgB))) ^ b_xor[nt2]));
#pragma unroll
                for (int mt = 0; mt < 4; mt++) {
                    mma16816(acc[mt][0], a[mt], bf[0][0], bf[0][1]);
                    mma16816(acc[mt][1], a[mt], bf[0][2], bf[0][3]);
                    mma16816(acc[mt][2], a[mt], bf[1][0], bf[1][1]);
                    mma16816(acc[mt][3], a[mt], bf[1][2], bf[1][3]);
                }
            }
        }

        // ---- D -> SMEM
#pragma unroll
        for (int mt = 0; mt < 4; mt++) {
#pragma unroll
            for (int nt = 0; nt < 4; nt++) {
                int r0 = 64 * mw + 16 * mt + (lane >> 2);
                int cc = 32 * nw + 8 * nt + 2 * (lane & 3);
                *(float2*)(dptr + r0 * D_ROW + cc * 4) =
                    make_float2(acc[mt][nt][0], acc[mt][nt][1]);
                *(float2*)(dptr + (r0 + 8) * D_ROW + cc * 4) =
                    make_float2(acc[mt][nt][2], acc[mt][nt][3]);
            }
        }
        __syncthreads();

        // ---- epilogue: thread = batch row
        const int b = tid;
        const int cls = d_xT[t * BB + b];
        const float4* Pp = (const float4*)(d_P + ((size_t)cls * HH + cta * HCPC) * 4);
        const char* drow = dptr + b * D_ROW;
        __nv_bfloat16 hb16[HCPC];
#pragma unroll
        for (int c = 0; c < HCPC; c++) {
            float4 dv = *(const float4*)(drow + c * 16);
            float4 pg = Pp[c];
            float f  = sigf(dv.x + pg.x);
            float ii = sigf(dv.y + pg.y);
            float gg = sigf(dv.z + pg.z);
            float oo = sigf(dv.w + pg.w);
            float Cn = fmaf(gg, ii, C[c] * f);
            Cn = (cls > 0) ? Cn : 0.0f;
            C[c] = Cn;
            float hv = oo * tanh_s(Cn);
            hb16[c] = __float2bfloat16(hv);
            if (t == SS - 1) d_hfin[(size_t)b * HH + cta * HCPC + c] = hv;
        }
        __nv_bfloat16* hd = d_hbf[(t + 1) & 1] + (size_t)b * HH + cta * HCPC;
        *(uint4*)hd       = *(uint4*)&hb16[0];
        *(uint4*)(hd + 8) = *(uint4*)&hb16[8];

        grid_sync_all(RGRID);
    }
}

// ---------------- head ----------------
__global__ void k_head(const float* __restrict__ Wph, const float* __restrict__ bp,
                       float* __restrict__ out) {
    __shared__ float h_s[HH];
    __shared__ float red[128];
    const int b = blockIdx.x;
    const int n = threadIdx.x;

    for (int i = n; i < HH; i += 128) h_s[i] = d_hfin[(size_t)b * HH + i];
    __syncthreads();

    float p = bp[n];
#pragma unroll 8
    for (int k = 0; k < HH; k++) p = fmaf(h_s[k], Wph[(size_t)k * NCC + n], p);

    red[n] = p;
    __syncthreads();
    for (int s = 64; s > 0; s >>= 1) {
        if (n < s) red[n] = fmaxf(red[n], red[n + s]);
        __syncthreads();
    }
    float mx = red[0];
    __syncthreads();
    red[n] = __expf(p - mx);
    __syncthreads();
    for (int s = 64; s > 0; s >>= 1) {
        if (n < s) red[n] += red[n + s];
        __syncthreads();
    }
    float lse = mx + logf(red[0]);
    out[(size_t)b * NCC + n] = p - lse;
}

// ---------------- launch ----------------
extern "C" void kernel_launch(void* const* d_in, const int* in_sizes, int n_in,
                              void* d_out, int out_size) {
    const int*   x   = (const int*)d_in[0];
    const float* emb = (const float*)d_in[1];
    const float* Wfx = (const float*)d_in[2];
    const float* Wfh = (const float*)d_in[3];
    const float* bf  = (const float*)d_in[4];
    const float* Wix = (const float*)d_in[5];
    const float* Wih = (const float*)d_in[6];
    const float* bi  = (const float*)d_in[7];
    const float* Wgx = (const float*)d_in[8];
    const float* Wgh = (const float*)d_in[9];
    const float* bg  = (const float*)d_in[10];
    const float* Wox = (const float*)d_in[11];
    const float* Woh = (const float*)d_in[12];
    const float* bo  = (const float*)d_in[13];
    const float* Wph = (const float*)d_in[14];
    const float* bp  = (const float*)d_in[15];
    float* out = (float*)d_out;

    cudaFuncSetAttribute(k_recur, cudaFuncAttributeMaxDynamicSharedMemorySize, SMEM_DYN);

    k_misc<<<256, 256>>>(x);
    k_pack<<<(HH * HH + 255) / 256, 256>>>(Wfh, Wih, Wgh, Woh);
    dim3 gP(8, 9);
    k_precomp<<<gP, 128>>>(emb, Wfx, Wix, Wgx, Wox, bf, bi, bg, bo);
    k_recur<<<RGRID, RTHREADS, SMEM_DYN>>>();
    k_head<<<NCC, 128>>>(Wph, bp, out);
}